// round 3
// baseline (speedup 1.0000x reference)
#include <cuda_runtime.h>
#include <cstdint>
#include <math.h>

#define BB 64
#define SS 128
#define HH 1024
#define VV 32000

// Output layout in d_out (float):
//   [0, 2048000)            output  [64, 32000]
//   [2048000, 2113536)      h_new   [1, 64, 1024]
//   [2113536, 2121728)      attn_w  [64, 1, 128]
#define OUT_OFF_H   2048000
#define OUT_OFF_AW  2113536

// ---------------- scratch (static __device__, no allocations) ----------------
__device__ float g_x[BB * HH];                 // embedded inputs
__device__ float g_gi_p[4 * BB * 3 * HH];      // split-K partials of gi
__device__ float g_gh_p[4 * BB * 3 * HH];      // split-K partials of gh
__device__ float g_cat[BB * 2 * HH];           // [h_new | context]
__device__ float g_qp[8 * BB * HH];            // split-K partials of q
__device__ float g_ccp[8 * BB * HH];           // split-K partials of concat gemm
__device__ float g_co[BB * HH];                // tanh(concat)

// Device-side scratch selector table (avoids any host-side symbol queries in
// kernel_launch; initialized at module load entirely on the device side).
#define SEL_X   0
#define SEL_GIP 1
#define SEL_GHP 2
#define SEL_CAT 3
#define SEL_QP  4
#define SEL_CCP 5
#define SEL_CO  6
__device__ float* const g_bufs[7] = { g_x, g_gi_p, g_gh_p, g_cat, g_qp, g_ccp, g_co };

// ---------------- f32x2 packed math helpers ----------------
__device__ __forceinline__ unsigned long long pack2(float lo, float hi) {
    unsigned long long r;
    asm("mov.b64 %0, {%1,%2};" : "=l"(r) : "f"(lo), "f"(hi));
    return r;
}
__device__ __forceinline__ void unpack2(unsigned long long v, float& lo, float& hi) {
    asm("mov.b64 {%0,%1}, %2;" : "=f"(lo), "=f"(hi) : "l"(v));
}
__device__ __forceinline__ unsigned long long fma2(unsigned long long a,
                                                   unsigned long long b,
                                                   unsigned long long c) {
    unsigned long long d;
    asm("fma.rn.f32x2 %0, %1, %2, %3;" : "=l"(d) : "l"(a), "l"(b), "l"(c));
    return d;
}

// ---------------- generic M=64 GEMM ----------------
// C[b,n] = sum_k A[b,k] * Wmat(n,k)            (W_TRANS=true,  W is [N,K] row-major)
// C[b,n] = sum_k A[b,k] * Wmat(k,n)            (W_TRANS=false, W is [K,N] row-major)
// a_sel/c_sel >= 0 pick a device scratch buffer; -1 uses the passed pointer.
// SPLITK>1: each blockIdx.y computes a K-slice into C + y*64*ldc (partials).
// Accumulation in packed f32x2 over batch pairs (bit-exact fp32).
template <int BN, int BK, bool W_TRANS, bool ADD_BIAS, int SPLITK>
__global__ __launch_bounds__(256) void gemm64(
    const float* __restrict__ A_in, int a_sel, int lda,
    const float* __restrict__ W, int ldw,
    const float* __restrict__ bias,
    float* __restrict__ C_in, int c_sel, int ldc,
    int N, int K)
{
    __shared__ __align__(16) float As[BK][64];
    __shared__ __align__(16) float Ws[BK][BN];

    const float* A = (a_sel >= 0) ? g_bufs[a_sel] : A_in;
    float*       C = (c_sel >= 0) ? g_bufs[c_sel] : C_in;

    const int tid = threadIdx.x;
    const int n0  = blockIdx.x * BN;
    const int Ks  = K / SPLITK;
    const int kb0 = blockIdx.y * Ks;

    float* Cp = C + (size_t)blockIdx.y * 64 * (size_t)ldc;

    const int cn = tid & 31;   // column group: 4 consecutive n
    const int rb = tid >> 5;   // row group: 8 consecutive b (4 pairs)

    unsigned long long acc[4][4];
#pragma unroll
    for (int m = 0; m < 4; m++)
#pragma unroll
        for (int j = 0; j < 4; j++) acc[m][j] = 0ULL;

    for (int kt = 0; kt < Ks; kt += BK) {
        const int kb = kb0 + kt;

        // ---- load A tile (64 x BK), store transposed As[k][b] ----
#pragma unroll
        for (int r = 0; r < (64 * BK / 4) / 256; r++) {
            int f  = tid + 256 * r;
            int b  = f >> 3;
            int kg = f & 7;
            float4 v = *(const float4*)(A + (size_t)b * lda + kb + kg * 4);
            As[kg * 4 + 0][b] = v.x;
            As[kg * 4 + 1][b] = v.y;
            As[kg * 4 + 2][b] = v.z;
            As[kg * 4 + 3][b] = v.w;
        }
        // ---- load W tile (BN x BK), store Ws[k][n] ----
        if (W_TRANS) {
#pragma unroll
            for (int r = 0; r < (BN * BK / 4) / 256; r++) {
                int f  = tid + 256 * r;
                int n  = f >> 3;
                int kg = f & 7;
                float4 v = *(const float4*)(W + (size_t)(n0 + n) * ldw + kb + kg * 4);
                Ws[kg * 4 + 0][n] = v.x;
                Ws[kg * 4 + 1][n] = v.y;
                Ws[kg * 4 + 2][n] = v.z;
                Ws[kg * 4 + 3][n] = v.w;
            }
        } else {
#pragma unroll
            for (int r = 0; r < (BN * BK / 4) / 256; r++) {
                int f  = tid + 256 * r;
                int kr = f / (BN / 4);
                int ng = f % (BN / 4);
                float4 v = *(const float4*)(W + (size_t)(kb + kr) * ldw + n0 + ng * 4);
                *(float4*)&Ws[kr][ng * 4] = v;
            }
        }
        __syncthreads();

        // ---- compute ----
#pragma unroll
        for (int k = 0; k < BK; k++) {
            unsigned long long a0 = *(const unsigned long long*)&As[k][rb * 8 + 0];
            unsigned long long a1 = *(const unsigned long long*)&As[k][rb * 8 + 2];
            unsigned long long a2 = *(const unsigned long long*)&As[k][rb * 8 + 4];
            unsigned long long a3 = *(const unsigned long long*)&As[k][rb * 8 + 6];
            float4 wv = *(const float4*)&Ws[k][cn * 4];
            unsigned long long w0 = pack2(wv.x, wv.x);
            unsigned long long w1 = pack2(wv.y, wv.y);
            unsigned long long w2 = pack2(wv.z, wv.z);
            unsigned long long w3 = pack2(wv.w, wv.w);
            acc[0][0] = fma2(a0, w0, acc[0][0]);
            acc[0][1] = fma2(a0, w1, acc[0][1]);
            acc[0][2] = fma2(a0, w2, acc[0][2]);
            acc[0][3] = fma2(a0, w3, acc[0][3]);
            acc[1][0] = fma2(a1, w0, acc[1][0]);
            acc[1][1] = fma2(a1, w1, acc[1][1]);
            acc[1][2] = fma2(a1, w2, acc[1][2]);
            acc[1][3] = fma2(a1, w3, acc[1][3]);
            acc[2][0] = fma2(a2, w0, acc[2][0]);
            acc[2][1] = fma2(a2, w1, acc[2][1]);
            acc[2][2] = fma2(a2, w2, acc[2][2]);
            acc[2][3] = fma2(a2, w3, acc[2][3]);
            acc[3][0] = fma2(a3, w0, acc[3][0]);
            acc[3][1] = fma2(a3, w1, acc[3][1]);
            acc[3][2] = fma2(a3, w2, acc[3][2]);
            acc[3][3] = fma2(a3, w3, acc[3][3]);
        }
        __syncthreads();
    }

    // ---- epilogue ----
    float4 bb = make_float4(0.f, 0.f, 0.f, 0.f);
    if (ADD_BIAS) bb = *(const float4*)(bias + n0 + cn * 4);
#pragma unroll
    for (int m = 0; m < 4; m++) {
        int b0 = rb * 8 + 2 * m;
        float lo[4], hi[4];
#pragma unroll
        for (int j = 0; j < 4; j++) unpack2(acc[m][j], lo[j], hi[j]);
        float4 vlo = make_float4(lo[0] + bb.x, lo[1] + bb.y, lo[2] + bb.z, lo[3] + bb.w);
        float4 vhi = make_float4(hi[0] + bb.x, hi[1] + bb.y, hi[2] + bb.z, hi[3] + bb.w);
        *(float4*)(Cp + (size_t)b0 * ldc + n0 + cn * 4)       = vlo;
        *(float4*)(Cp + (size_t)(b0 + 1) * ldc + n0 + cn * 4) = vhi;
    }
}

// ---------------- embedding gather ----------------
__global__ void gather_x(const int* __restrict__ seq, const float* __restrict__ emb) {
    int b = blockIdx.x;
    int row = seq[b];
    const float4* src = (const float4*)(emb + (size_t)row * HH);
    float4* dst = (float4*)(g_x + b * HH);
    dst[threadIdx.x] = src[threadIdx.x];   // 256 threads * float4 = 1024 floats
}

// ---------------- GRU gate combine (reduces split-K partials) ----------------
__global__ void gru_combine(const float* __restrict__ lh,
                            const float* __restrict__ b_ih,
                            const float* __restrict__ b_hh,
                            float* __restrict__ out) {
    int b = blockIdx.x;
#pragma unroll
    for (int i = 0; i < 4; i++) {
        int h = threadIdx.x + 256 * i;
        float gir = 0.f, giz = 0.f, gin = 0.f, ghr = 0.f, ghz = 0.f, ghn = 0.f;
#pragma unroll
        for (int sl = 0; sl < 4; sl++) {
            const float* pi = g_gi_p + sl * (BB * 3 * HH) + b * 3 * HH;
            const float* ph = g_gh_p + sl * (BB * 3 * HH) + b * 3 * HH;
            gir += pi[h];          ghr += ph[h];
            giz += pi[HH + h];     ghz += ph[HH + h];
            gin += pi[2 * HH + h]; ghn += ph[2 * HH + h];
        }
        float r = 1.f / (1.f + expf(-(gir + b_ih[h] + ghr + b_hh[h])));
        float z = 1.f / (1.f + expf(-(giz + b_ih[HH + h] + ghz + b_hh[HH + h])));
        float n = tanhf(gin + b_ih[2 * HH + h] + r * (ghn + b_hh[2 * HH + h]));
        float hv = lh[b * HH + h];
        float hn = (1.f - z) * n + z * hv;
        g_cat[b * 2 * HH + h] = hn;
        out[OUT_OFF_H + b * HH + h] = hn;
    }
}

// ---------------- attention: energies + softmax + context ----------------
// One block per batch row. q comes in as 8 split-K partials.
__global__ __launch_bounds__(256) void attention(const float* __restrict__ enc,
                                                 float* __restrict__ out) {
    __shared__ float q_s[HH];
    __shared__ float e_s[SS];
    __shared__ float w_s[SS];
    int b = blockIdx.x;
    int tid = threadIdx.x;

#pragma unroll
    for (int i = 0; i < 4; i++) {
        int h = tid + 256 * i;
        float v = 0.f;
#pragma unroll
        for (int sl = 0; sl < 8; sl++) v += g_qp[sl * (BB * HH) + b * HH + h];
        q_s[h] = v;
    }
    __syncthreads();

    int warp = tid >> 5, lane = tid & 31;
    for (int i = 0; i < 16; i++) {
        int s = warp * 16 + i;
        const float* p = enc + ((size_t)s * BB + b) * HH;
        float acc = 0.f;
#pragma unroll 8
        for (int j = 0; j < 32; j++) acc += q_s[lane + 32 * j] * p[lane + 32 * j];
#pragma unroll
        for (int o = 16; o; o >>= 1) acc += __shfl_xor_sync(0xffffffffu, acc, o);
        if (lane == 0) e_s[s] = acc;
    }
    __syncthreads();

    if (tid < 32) {
        float e0 = e_s[tid], e1 = e_s[tid + 32], e2 = e_s[tid + 64], e3 = e_s[tid + 96];
        float m = fmaxf(fmaxf(e0, e1), fmaxf(e2, e3));
#pragma unroll
        for (int o = 16; o; o >>= 1) m = fmaxf(m, __shfl_xor_sync(0xffffffffu, m, o));
        float x0 = expf(e0 - m), x1 = expf(e1 - m), x2 = expf(e2 - m), x3 = expf(e3 - m);
        float sum = x0 + x1 + x2 + x3;
#pragma unroll
        for (int o = 16; o; o >>= 1) sum += __shfl_xor_sync(0xffffffffu, sum, o);
        float inv = 1.f / sum;
        w_s[tid]      = x0 * inv;
        w_s[tid + 32] = x1 * inv;
        w_s[tid + 64] = x2 * inv;
        w_s[tid + 96] = x3 * inv;
        out[OUT_OFF_AW + b * SS + tid]      = x0 * inv;
        out[OUT_OFF_AW + b * SS + tid + 32] = x1 * inv;
        out[OUT_OFF_AW + b * SS + tid + 64] = x2 * inv;
        out[OUT_OFF_AW + b * SS + tid + 96] = x3 * inv;
    }
    __syncthreads();

    float a0 = 0.f, a1 = 0.f, a2 = 0.f, a3 = 0.f;
    const float* encb = enc + (size_t)b * HH;
#pragma unroll 4
    for (int s = 0; s < SS; s++) {
        float wv = w_s[s];
        const float* p = encb + (size_t)s * BB * HH;
        a0 += wv * p[tid];
        a1 += wv * p[tid + 256];
        a2 += wv * p[tid + 512];
        a3 += wv * p[tid + 768];
    }
    g_cat[b * 2 * HH + HH + tid]       = a0;
    g_cat[b * 2 * HH + HH + tid + 256] = a1;
    g_cat[b * 2 * HH + HH + tid + 512] = a2;
    g_cat[b * 2 * HH + HH + tid + 768] = a3;
}

// ---------------- concat reduce + tanh ----------------
__global__ void concat_reduce(const float* __restrict__ concat_b) {
    int b = blockIdx.x;
#pragma unroll
    for (int i = 0; i < 4; i++) {
        int h = threadIdx.x + 256 * i;
        float v = concat_b[h];
#pragma unroll
        for (int sl = 0; sl < 8; sl++) v += g_ccp[sl * (BB * HH) + b * HH + h];
        g_co[b * HH + h] = tanhf(v);
    }
}

// ---------------- launch (kernel launches ONLY; no host CUDA API) ----------------
extern "C" void kernel_launch(void* const* d_in, const int* in_sizes, int n_in,
                              void* d_out, int out_size) {
    (void)in_sizes; (void)n_in; (void)out_size;
    const int*   seq      = (const int*)d_in[0];
    const float* lh       = (const float*)d_in[1];
    const float* enc      = (const float*)d_in[2];
    const float* emb      = (const float*)d_in[3];
    const float* W_ih     = (const float*)d_in[4];
    const float* W_hh     = (const float*)d_in[5];
    const float* b_ih     = (const float*)d_in[6];
    const float* b_hh     = (const float*)d_in[7];
    const float* attn_W   = (const float*)d_in[8];
    // d_in[9] attn_b: dropped exactly (softmax shift invariance)
    const float* concat_W = (const float*)d_in[10];
    const float* concat_b = (const float*)d_in[11];
    const float* out_W    = (const float*)d_in[12];
    const float* out_b    = (const float*)d_in[13];
    float* out = (float*)d_out;

    // 1) x = emb[seq]
    gather_x<<<BB, 256>>>(seq, emb);

    // 2) gi = x @ W_ih^T (split-K=4 partials), gh = h @ W_hh^T
    gemm64<128, 32, true, false, 4><<<dim3(3 * HH / 128, 4), 256>>>(
        nullptr, SEL_X, HH, W_ih, HH, nullptr, nullptr, SEL_GIP, 3 * HH, 3 * HH, HH);
    gemm64<128, 32, true, false, 4><<<dim3(3 * HH / 128, 4), 256>>>(
        lh, -1, HH, W_hh, HH, nullptr, nullptr, SEL_GHP, 3 * HH, 3 * HH, HH);

    // 3) GRU combine -> h_new (into g_cat[:, :H] and d_out)
    gru_combine<<<BB, 256>>>(lh, b_ih, b_hh, out);

    // 4) q = h_new @ attn_W  (NN orientation, split-K=8)
    gemm64<128, 32, false, false, 8><<<dim3(HH / 128, 8), 256>>>(
        nullptr, SEL_CAT, 2 * HH, attn_W, HH, nullptr, nullptr, SEL_QP, HH, HH, HH);

    // 5) energies / softmax / context  (context into g_cat[:, H:])
    attention<<<BB, 256>>>(enc, out);

    // 6) concat GEMM (split-K=8), then reduce + tanh
    gemm64<128, 32, true, false, 8><<<dim3(HH / 128, 8), 256>>>(
        nullptr, SEL_CAT, 2 * HH, concat_W, 2 * HH, nullptr, nullptr, SEL_CCP, HH, HH, 2 * HH);
    concat_reduce<<<BB, 256>>>(concat_b);

    // 7) output = concat_out @ out_W^T + out_b   (dominant GEMM)
    gemm64<128, 32, true, true, 1><<<dim3(VV / 128, 1), 256>>>(
        nullptr, SEL_CO, HH, out_W, HH, out_b, out, -1, VV, VV, HH);
}

// round 5
// speedup vs baseline: 1.9134x; 1.9134x over previous
#include <cuda_runtime.h>
#include <cstdint>
#include <math.h>

#define BB 64
#define SS 128
#define HH 1024
#define VV 32000

// Output layout in d_out (float):
//   [0, 2048000)            output  [64, 32000]
//   [2048000, 2113536)      h_new   [1, 64, 1024]
//   [2113536, 2121728)      attn_w  [64, 1, 128]
#define OUT_OFF_H   2048000
#define OUT_OFF_AW  2113536

// ---------------- scratch (static __device__, no allocations) ----------------
__device__ float g_x[BB * HH];                 // embedded inputs
__device__ float g_gi_p[4 * BB * 3 * HH];      // split-K partials of gi
__device__ float g_gh_p[4 * BB * 3 * HH];      // split-K partials of gh
__device__ float g_cat[BB * 2 * HH];           // [h_new | context]
__device__ float g_qp[8 * BB * HH];            // split-K partials of q
__device__ float g_ccp[8 * BB * HH];           // split-K partials of concat gemm
__device__ float g_co[BB * HH];                // tanh(concat), pre-rounded to tf32
__device__ float g_energy[BB * SS];            // attention energies

// Device-side scratch selector table (kernel_launch stays host-API-free).
#define SEL_X   0
#define SEL_GIP 1
#define SEL_GHP 2
#define SEL_CAT 3
#define SEL_QP  4
#define SEL_CCP 5
#define SEL_CO  6
__device__ float* const g_bufs[7] = { g_x, g_gi_p, g_gh_p, g_cat, g_qp, g_ccp, g_co };

// ---------------- f32x2 packed math helpers ----------------
__device__ __forceinline__ unsigned long long pack2(float lo, float hi) {
    unsigned long long r;
    asm("mov.b64 %0, {%1,%2};" : "=l"(r) : "f"(lo), "f"(hi));
    return r;
}
__device__ __forceinline__ void unpack2(unsigned long long v, float& lo, float& hi) {
    asm("mov.b64 {%0,%1}, %2;" : "=f"(lo), "=f"(hi) : "l"(v));
}
__device__ __forceinline__ unsigned long long fma2(unsigned long long a,
                                                   unsigned long long b,
                                                   unsigned long long c) {
    unsigned long long d;
    asm("fma.rn.f32x2 %0, %1, %2, %3;" : "=l"(d) : "l"(a), "l"(b), "l"(c));
    return d;
}
__device__ __forceinline__ uint32_t to_tf32(float f) {
    uint32_t u;
    asm("cvt.rna.tf32.f32 %0, %1;" : "=r"(u) : "f"(f));
    return u;
}

// ---------------- generic M=64 fp32 GEMM (small GEMMs) ----------------
// C[b,n] = sum_k A[b,k] * Wmat(n,k)   (W_TRANS=true,  W is [N,K] row-major)
// C[b,n] = sum_k A[b,k] * Wmat(k,n)   (W_TRANS=false, W is [K,N] row-major)
// a_sel/c_sel >= 0 pick a device scratch buffer; -1 uses the passed pointer.
// DUAL: blockIdx.z==1 switches to the second (A2/W2/C2) problem.
// SPLITK>1: blockIdx.y computes a K-slice into C + y*64*ldc (partials).
template <int BN, int BK, bool W_TRANS, bool ADD_BIAS, int SPLITK, bool DUAL>
__global__ __launch_bounds__(256) void gemm64(
    const float* __restrict__ A_in, int a_sel, int lda,
    const float* __restrict__ W_in, int ldw,
    const float* __restrict__ bias,
    float* __restrict__ C_in, int c_sel, int ldc,
    int N, int K,
    const float* __restrict__ A2, int a_sel2,
    const float* __restrict__ W2, int c_sel2)
{
    __shared__ __align__(16) float As[BK][64];
    __shared__ __align__(16) float Ws[BK][BN];

    const float* A = (a_sel >= 0) ? g_bufs[a_sel] : A_in;
    const float* W = W_in;
    float*       C = (c_sel >= 0) ? g_bufs[c_sel] : C_in;
    if (DUAL && blockIdx.z == 1) {
        A = (a_sel2 >= 0) ? g_bufs[a_sel2] : A2;
        W = W2;
        C = g_bufs[c_sel2];
    }

    const int tid = threadIdx.x;
    const int n0  = blockIdx.x * BN;
    const int Ks  = K / SPLITK;
    const int kb0 = blockIdx.y * Ks;

    float* Cp = C + (size_t)blockIdx.y * 64 * (size_t)ldc;

    const int cn = tid & 31;   // column group: 4 consecutive n
    const int rb = tid >> 5;   // row group: 8 consecutive b (4 pairs)

    unsigned long long acc[4][4];
#pragma unroll
    for (int m = 0; m < 4; m++)
#pragma unroll
        for (int j = 0; j < 4; j++) acc[m][j] = 0ULL;

    for (int kt = 0; kt < Ks; kt += BK) {
        const int kb = kb0 + kt;

#pragma unroll
        for (int r = 0; r < (64 * BK / 4) / 256; r++) {
            int f  = tid + 256 * r;
            int b  = f >> 3;
            int kg = f & 7;
            float4 v = *(const float4*)(A + (size_t)b * lda + kb + kg * 4);
            As[kg * 4 + 0][b] = v.x;
            As[kg * 4 + 1][b] = v.y;
            As[kg * 4 + 2][b] = v.z;
            As[kg * 4 + 3][b] = v.w;
        }
        if (W_TRANS) {
#pragma unroll
            for (int r = 0; r < (BN * BK / 4) / 256; r++) {
                int f  = tid + 256 * r;
                int n  = f >> 3;
                int kg = f & 7;
                float4 v = *(const float4*)(W + (size_t)(n0 + n) * ldw + kb + kg * 4);
                Ws[kg * 4 + 0][n] = v.x;
                Ws[kg * 4 + 1][n] = v.y;
                Ws[kg * 4 + 2][n] = v.z;
                Ws[kg * 4 + 3][n] = v.w;
            }
        } else {
#pragma unroll
            for (int r = 0; r < (BN * BK / 4) / 256; r++) {
                int f  = tid + 256 * r;
                int kr = f / (BN / 4);
                int ng = f % (BN / 4);
                float4 v = *(const float4*)(W + (size_t)(kb + kr) * ldw + n0 + ng * 4);
                *(float4*)&Ws[kr][ng * 4] = v;
            }
        }
        __syncthreads();

#pragma unroll
        for (int k = 0; k < BK; k++) {
            unsigned long long a0 = *(const unsigned long long*)&As[k][rb * 8 + 0];
            unsigned long long a1 = *(const unsigned long long*)&As[k][rb * 8 + 2];
            unsigned long long a2 = *(const unsigned long long*)&As[k][rb * 8 + 4];
            unsigned long long a3 = *(const unsigned long long*)&As[k][rb * 8 + 6];
            float4 wv = *(const float4*)&Ws[k][cn * 4];
            unsigned long long w0 = pack2(wv.x, wv.x);
            unsigned long long w1 = pack2(wv.y, wv.y);
            unsigned long long w2 = pack2(wv.z, wv.z);
            unsigned long long w3 = pack2(wv.w, wv.w);
            acc[0][0] = fma2(a0, w0, acc[0][0]);
            acc[0][1] = fma2(a0, w1, acc[0][1]);
            acc[0][2] = fma2(a0, w2, acc[0][2]);
            acc[0][3] = fma2(a0, w3, acc[0][3]);
            acc[1][0] = fma2(a1, w0, acc[1][0]);
            acc[1][1] = fma2(a1, w1, acc[1][1]);
            acc[1][2] = fma2(a1, w2, acc[1][2]);
            acc[1][3] = fma2(a1, w3, acc[1][3]);
            acc[2][0] = fma2(a2, w0, acc[2][0]);
            acc[2][1] = fma2(a2, w1, acc[2][1]);
            acc[2][2] = fma2(a2, w2, acc[2][2]);
            acc[2][3] = fma2(a2, w3, acc[2][3]);
            acc[3][0] = fma2(a3, w0, acc[3][0]);
            acc[3][1] = fma2(a3, w1, acc[3][1]);
            acc[3][2] = fma2(a3, w2, acc[3][2]);
            acc[3][3] = fma2(a3, w3, acc[3][3]);
        }
        __syncthreads();
    }

    float4 bb = make_float4(0.f, 0.f, 0.f, 0.f);
    if (ADD_BIAS) bb = *(const float4*)(bias + n0 + cn * 4);
#pragma unroll
    for (int m = 0; m < 4; m++) {
        int b0 = rb * 8 + 2 * m;
        float lo[4], hi[4];
#pragma unroll
        for (int j = 0; j < 4; j++) unpack2(acc[m][j], lo[j], hi[j]);
        float4 vlo = make_float4(lo[0] + bb.x, lo[1] + bb.y, lo[2] + bb.z, lo[3] + bb.w);
        float4 vhi = make_float4(hi[0] + bb.x, hi[1] + bb.y, hi[2] + bb.z, hi[3] + bb.w);
        *(float4*)(Cp + (size_t)b0 * ldc + n0 + cn * 4)       = vlo;
        *(float4*)(Cp + (size_t)(b0 + 1) * ldc + n0 + cn * 4) = vhi;
    }
}

// ---------------- tf32 tensor-core output GEMM ----------------
// C[64, 32000] = g_co[64,1024] @ W[32000,1024]^T + bias.
// Block: 128 N-cols, 256 threads (8 warps in 2(M)x4(N)), cp.async 2-stage,
// XOR-swizzled smem (16B atoms), m16n8k8 tf32 mma. Grid 250, 2 blocks/SM
// resident -> single wave.
#define CP16(dst_u32, src_ptr) \
    asm volatile("cp.async.cg.shared.global [%0], [%1], 16;" :: "r"(dst_u32), "l"(src_ptr))

__global__ __launch_bounds__(256, 2) void gemm_out_tf32(
    const float* __restrict__ W,
    const float* __restrict__ bias,
    float* __restrict__ C)
{
    __shared__ __align__(16) float As[2][64 * 32];
    __shared__ __align__(16) float Ws[2][128 * 32];

    const int tid  = threadIdx.x;
    const int n0   = blockIdx.x * 128;
    const int lane = tid & 31, wrp = tid >> 5;
    const int wm = wrp & 1, wn = wrp >> 1;
    const int g = lane >> 2, tig = lane & 3;

    const uint32_t asb = (uint32_t)__cvta_generic_to_shared(&As[0][0]);
    const uint32_t wsb = (uint32_t)__cvta_generic_to_shared(&Ws[0][0]);

    float acc[2][4][4];
#pragma unroll
    for (int mt = 0; mt < 2; mt++)
#pragma unroll
        for (int nt = 0; nt < 4; nt++)
#pragma unroll
            for (int j = 0; j < 4; j++) acc[mt][nt][j] = 0.f;

#define ISSUE_LOADS(stage, kt)                                                     \
    do {                                                                           \
        _Pragma("unroll")                                                          \
        for (int r = 0; r < 2; r++) {                                              \
            int c = tid + 256 * r;                                                 \
            int row = c >> 3, seg = c & 7;                                         \
            int sw = seg ^ (row & 7);                                              \
            uint32_t dst = asb + (uint32_t)(((stage) * 2048 + row * 32 + sw * 4) * 4); \
            const float* src = g_co + row * 1024 + (kt) + seg * 4;                 \
            CP16(dst, src);                                                        \
        }                                                                          \
        _Pragma("unroll")                                                          \
        for (int r = 0; r < 4; r++) {                                              \
            int c = tid + 256 * r;                                                 \
            int row = c >> 3, seg = c & 7;                                         \
            int sw = seg ^ (row & 7);                                              \
            uint32_t dst = wsb + (uint32_t)(((stage) * 4096 + row * 32 + sw * 4) * 4); \
            const float* src = W + (size_t)(n0 + row) * 1024 + (kt) + seg * 4;     \
            CP16(dst, src);                                                        \
        }                                                                          \
        asm volatile("cp.async.commit_group;");                                    \
    } while (0)

    ISSUE_LOADS(0, 0);

    for (int t = 0; t < 32; t++) {
        if (t + 1 < 32) {
            ISSUE_LOADS((t + 1) & 1, (t + 1) * 32);
            asm volatile("cp.async.wait_group 1;");
        } else {
            asm volatile("cp.async.wait_group 0;");
        }
        __syncthreads();

        const float* Asb = As[t & 1];
        const float* Wsb = Ws[t & 1];
#pragma unroll
        for (int kc = 0; kc < 4; kc++) {
            uint32_t a[2][4];
#pragma unroll
            for (int mt = 0; mt < 2; mt++) {
                int r0 = wm * 32 + mt * 16 + g;
                int r1 = r0 + 8;
                a[mt][0] = __float_as_uint(Asb[r0 * 32 + ((2 * kc)     ^ (r0 & 7)) * 4 + tig]);
                a[mt][1] = __float_as_uint(Asb[r1 * 32 + ((2 * kc)     ^ (r1 & 7)) * 4 + tig]);
                a[mt][2] = __float_as_uint(Asb[r0 * 32 + ((2 * kc + 1) ^ (r0 & 7)) * 4 + tig]);
                a[mt][3] = __float_as_uint(Asb[r1 * 32 + ((2 * kc + 1) ^ (r1 & 7)) * 4 + tig]);
            }
#pragma unroll
            for (int nt = 0; nt < 4; nt++) {
                int nr = wn * 32 + nt * 8 + g;
                uint32_t b0 = to_tf32(Wsb[nr * 32 + ((2 * kc)     ^ (nr & 7)) * 4 + tig]);
                uint32_t b1 = to_tf32(Wsb[nr * 32 + ((2 * kc + 1) ^ (nr & 7)) * 4 + tig]);
#pragma unroll
                for (int mt = 0; mt < 2; mt++) {
                    asm("mma.sync.aligned.m16n8k8.row.col.f32.tf32.tf32.f32 "
                        "{%0,%1,%2,%3}, {%4,%5,%6,%7}, {%8,%9}, {%0,%1,%2,%3};"
                        : "+f"(acc[mt][nt][0]), "+f"(acc[mt][nt][1]),
                          "+f"(acc[mt][nt][2]), "+f"(acc[mt][nt][3])
                        : "r"(a[mt][0]), "r"(a[mt][1]), "r"(a[mt][2]), "r"(a[mt][3]),
                          "r"(b0), "r"(b1));
                }
            }
        }
        __syncthreads();
    }

#pragma unroll
    for (int nt = 0; nt < 4; nt++) {
        int col = n0 + wn * 32 + nt * 8 + 2 * tig;
        float2 bv = *(const float2*)(bias + col);
#pragma unroll
        for (int mt = 0; mt < 2; mt++) {
            int r0 = wm * 32 + mt * 16 + g;
            float2 v0 = make_float2(acc[mt][nt][0] + bv.x, acc[mt][nt][1] + bv.y);
            float2 v1 = make_float2(acc[mt][nt][2] + bv.x, acc[mt][nt][3] + bv.y);
            *(float2*)(C + (size_t)r0 * VV + col)       = v0;
            *(float2*)(C + (size_t)(r0 + 8) * VV + col) = v1;
        }
    }
}

// ---------------- embedding gather ----------------
__global__ void gather_x(const int* __restrict__ seq, const float* __restrict__ emb) {
    int b = blockIdx.x;
    int row = seq[b];
    const float4* src = (const float4*)(emb + (size_t)row * HH);
    float4* dst = (float4*)(g_x + b * HH);
    dst[threadIdx.x] = src[threadIdx.x];
}

// ---------------- GRU gate combine (grid 64x4, one h per thread) ----------------
__global__ void gru_combine(const float* __restrict__ lh,
                            const float* __restrict__ b_ih,
                            const float* __restrict__ b_hh,
                            float* __restrict__ out) {
    int b = blockIdx.x;
    int h = blockIdx.y * 256 + threadIdx.x;
    float gir = 0.f, giz = 0.f, gin = 0.f, ghr = 0.f, ghz = 0.f, ghn = 0.f;
#pragma unroll
    for (int sl = 0; sl < 4; sl++) {
        const float* pi = g_gi_p + sl * (BB * 3 * HH) + b * 3 * HH;
        const float* ph = g_gh_p + sl * (BB * 3 * HH) + b * 3 * HH;
        gir += pi[h];          ghr += ph[h];
        giz += pi[HH + h];     ghz += ph[HH + h];
        gin += pi[2 * HH + h]; ghn += ph[2 * HH + h];
    }
    float r = 1.f / (1.f + expf(-(gir + b_ih[h] + ghr + b_hh[h])));
    float z = 1.f / (1.f + expf(-(giz + b_ih[HH + h] + ghz + b_hh[HH + h])));
    float n = tanhf(gin + b_ih[2 * HH + h] + r * (ghn + b_hh[2 * HH + h]));
    float hv = lh[b * HH + h];
    float hn = (1.f - z) * n + z * hv;
    g_cat[b * 2 * HH + h] = hn;
    out[OUT_OFF_H + b * HH + h] = hn;
}

// ---------------- energies: grid (64, 4 s-chunks), 8 warps x 4 s each ----------------
__global__ __launch_bounds__(256) void energies_k(const float* __restrict__ enc) {
    __shared__ float q_s[HH];
    int b = blockIdx.x, sc = blockIdx.y;
    int tid = threadIdx.x;

#pragma unroll
    for (int i = 0; i < 4; i++) {
        int h = tid + 256 * i;
        float v = 0.f;
#pragma unroll
        for (int sl = 0; sl < 8; sl++) v += g_qp[sl * (BB * HH) + b * HH + h];
        q_s[h] = v;
    }
    __syncthreads();

    int warp = tid >> 5, lane = tid & 31;
#pragma unroll
    for (int i = 0; i < 4; i++) {
        int s = sc * 32 + warp * 4 + i;
        const float* p = enc + ((size_t)s * BB + b) * HH;
        float acc = 0.f;
#pragma unroll 8
        for (int j = 0; j < 32; j++) acc += q_s[lane + 32 * j] * p[lane + 32 * j];
#pragma unroll
        for (int o = 16; o; o >>= 1) acc += __shfl_xor_sync(0xffffffffu, acc, o);
        if (lane == 0) g_energy[b * SS + s] = acc;
    }
}

// ---------------- context (+softmax, +attn_w write): grid (64, 4 h-chunks) ----------------
__global__ __launch_bounds__(256) void context_k(const float* __restrict__ enc,
                                                 float* __restrict__ out) {
    __shared__ float e_s[SS];
    __shared__ float w_s[SS];
    int b = blockIdx.x, hc = blockIdx.y;
    int tid = threadIdx.x;

    if (tid < SS) e_s[tid] = g_energy[b * SS + tid];
    __syncthreads();

    // every thread computes identical max/sum serially (deterministic)
    float m = -1e30f;
#pragma unroll 8
    for (int s = 0; s < SS; s++) m = fmaxf(m, e_s[s]);
    float sum = 0.f;
#pragma unroll 8
    for (int s = 0; s < SS; s++) sum += expf(e_s[s] - m);
    float inv = 1.f / sum;
    if (tid < SS) {
        float wv = expf(e_s[tid] - m) * inv;
        w_s[tid] = wv;
        if (hc == 0) out[OUT_OFF_AW + b * SS + tid] = wv;
    }
    __syncthreads();

    int h = hc * 256 + tid;
    float acc = 0.f;
    const float* encb = enc + (size_t)b * HH + h;
#pragma unroll 4
    for (int s = 0; s < SS; s++)
        acc += w_s[s] * encb[(size_t)s * BB * HH];
    g_cat[b * 2 * HH + HH + h] = acc;
}

// ---------------- concat reduce + tanh (+pre-round to tf32) ----------------
__global__ void concat_reduce(const float* __restrict__ concat_b) {
    int b = blockIdx.x;
    int h = blockIdx.y * 256 + threadIdx.x;
    float v = concat_b[h];
#pragma unroll
    for (int sl = 0; sl < 8; sl++) v += g_ccp[sl * (BB * HH) + b * HH + h];
    float t = tanhf(v);
    g_co[b * HH + h] = __uint_as_float(to_tf32(t));   // rna-rounded tf32 (fp32 bits)
}

// ---------------- launch (kernel launches ONLY) ----------------
extern "C" void kernel_launch(void* const* d_in, const int* in_sizes, int n_in,
                              void* d_out, int out_size) {
    (void)in_sizes; (void)n_in; (void)out_size;
    const int*   seq      = (const int*)d_in[0];
    const float* lh       = (const float*)d_in[1];
    const float* enc      = (const float*)d_in[2];
    const float* emb      = (const float*)d_in[3];
    const float* W_ih     = (const float*)d_in[4];
    const float* W_hh     = (const float*)d_in[5];
    const float* b_ih     = (const float*)d_in[6];
    const float* b_hh     = (const float*)d_in[7];
    const float* attn_W   = (const float*)d_in[8];
    // d_in[9] attn_b: dropped exactly (softmax shift invariance)
    const float* concat_W = (const float*)d_in[10];
    const float* concat_b = (const float*)d_in[11];
    const float* out_W    = (const float*)d_in[12];
    const float* out_b    = (const float*)d_in[13];
    float* out = (float*)d_out;

    // 1) x = emb[seq]
    gather_x<<<BB, 256>>>(seq, emb);

    // 2) gates: gi = x @ W_ih^T  and  gh = h @ W_hh^T  (one dual launch, split-K=4)
    gemm64<128, 32, true, false, 4, true><<<dim3(3 * HH / 128, 4, 2), 256>>>(
        nullptr, SEL_X, HH, W_ih, HH, nullptr, nullptr, SEL_GIP, 3 * HH, 3 * HH, HH,
        lh, -1, W_hh, SEL_GHP);

    // 3) GRU combine -> h_new
    gru_combine<<<dim3(BB, 4), 256>>>(lh, b_ih, b_hh, out);

    // 4) q = h_new @ attn_W (split-K=8)
    gemm64<128, 32, false, false, 8, false><<<dim3(HH / 128, 8), 256>>>(
        nullptr, SEL_CAT, 2 * HH, attn_W, HH, nullptr, nullptr, SEL_QP, HH, HH, HH,
        nullptr, -1, nullptr, -1);

    // 5) energies, then softmax+context
    energies_k<<<dim3(BB, 4), 256>>>(enc);
    context_k<<<dim3(BB, 4), 256>>>(enc, out);

    // 6) concat GEMM (split-K=8) + reduce + tanh (+tf32 round)
    gemm64<128, 32, true, false, 8, false><<<dim3(HH / 128, 8), 256>>>(
        nullptr, SEL_CAT, 2 * HH, concat_W, 2 * HH, nullptr, nullptr, SEL_CCP, HH, HH, 2 * HH,
        nullptr, -1, nullptr, -1);
    concat_reduce<<<dim3(BB, 4), 256>>>(concat_b);

    // 7) output = concat_out @ out_W^T + out_b   (tf32 tensor cores)
    gemm_out_tf32<<<VV / 128, 256>>>(out_W, out_b, out);
}